// round 16
// baseline (speedup 1.0000x reference)
#include <cuda_runtime.h>

#define D      128
#define KS     9
#define L_IN   4096
#define L_OUT  4072
#define T_EFF  25
#define T12    17
#define BATCH  128
#define ROW    (D * KS)   // 1152
#define HALF   2036       // L_OUT / 2
#define HW     509        // HALF / 4 (words per half)

// Inter-phase tables
__device__ float d_g1T[36 * D];
__device__ float d_g2T[68 * D];
__device__ float d_G  [100 * D];
__device__ float d_bb2[D];
__device__ float d_beff[D];
// Token-side precomputed per row (written by pre1)
__device__ __align__(16) unsigned d_tok[BATCH * 1032];
__device__ __align__(16) unsigned d_pat[BATCH * 1032];
__device__ __align__(16) float    d_cnt[BATCH * 128];
// Cross-CTA exchange (pair of halves per row)
__device__ __align__(16) float    d_xch[BATCH * 2 * 80];
// Pair barrier (generation counters: replay-safe, monotonic)
__device__ unsigned p_cnt[BATCH];
__device__ unsigned p_gen[BATCH];

__device__ __forceinline__ float warp_sum(float s) {
    #pragma unroll
    for (int o = 16; o; o >>= 1) s += __shfl_xor_sync(0xffffffffu, s, o);
    return s;
}

// ---------------------------------------------------------------------------
// pre1: c1 = bid. g1T + ALL token-side preprocessing for row bid.
__global__ __launch_bounds__(1024) void k_pre1(
    const float* __restrict__ w1, const float* __restrict__ emb,
    const int*   __restrict__ tokens)
{
    __shared__ float ws[ROW];
    __shared__ float es[4 * D];
    __shared__ unsigned tok_u[1032];
    __shared__ int cnti[4];
    unsigned char* tok = (unsigned char*)tok_u;

    cudaTriggerProgrammaticLaunchCompletion();

    const int bid = blockIdx.x, tid = threadIdx.x;
    const int lane = tid & 31, warp = tid >> 5;

    const float* wrow = w1 + bid * ROW;
    for (int i = tid; i < ROW; i += 1024) ws[i] = wrow[i];
    if (tid < 512) es[tid] = emb[tid];

    {
        const int4* tb4 = (const int4*)(tokens + bid * L_IN);
        int4 w = tb4[tid];
        unsigned pk = (unsigned)w.x | ((unsigned)w.y << 8) |
                      ((unsigned)w.z << 16) | ((unsigned)w.w << 24);
        tok_u[tid] = pk;
        d_tok[bid * 1032 + tid] = pk;
    }
    if (tid < 8) { tok_u[1024 + tid] = 0; d_tok[bid * 1032 + 1024 + tid] = 0; }
    if (tid < 4) cnti[tid] = 0;
    __syncthreads();

    for (int i = tid; i < 1030; i += 1024) {
        unsigned w0 = tok_u[i], w1w = tok_u[i + 1];
        unsigned p0 = ((w0 & 0x03030303u) * 0x40100401u) >> 24;
        unsigned f1 = __funnelshift_r(w0, w1w, 8);
        unsigned p1 = ((f1 & 0x03030303u) * 0x40100401u) >> 24;
        unsigned f2 = __funnelshift_r(w0, w1w, 16);
        unsigned p2 = ((f2 & 0x03030303u) * 0x40100401u) >> 24;
        unsigned f3 = __funnelshift_r(w0, w1w, 24);
        unsigned p3 = ((f3 & 0x03030303u) * 0x40100401u) >> 24;
        d_pat[bid * 1032 + i] = p0 | (p1 << 8) | (p2 << 16) | (p3 << 24);
    }
    if (tid < 2) d_pat[bid * 1032 + 1030 + tid] = 0;

    {
        unsigned u = tok_u[tid];
        int l0 = 0, l1 = 0, l2 = 0, l3 = 0;
        #pragma unroll
        for (int j = 0; j < 4; j++) {
            int v = (u >> (8 * j)) & 3;
            l0 += (v == 0); l1 += (v == 1); l2 += (v == 2); l3 += (v == 3);
        }
        #pragma unroll
        for (int o = 16; o; o >>= 1) {
            l0 += __shfl_xor_sync(0xffffffffu, l0, o);
            l1 += __shfl_xor_sync(0xffffffffu, l1, o);
            l2 += __shfl_xor_sync(0xffffffffu, l2, o);
            l3 += __shfl_xor_sync(0xffffffffu, l3, o);
        }
        if (lane == 0) {
            atomicAdd(&cnti[0], l0); atomicAdd(&cnti[1], l1);
            atomicAdd(&cnti[2], l2); atomicAdd(&cnti[3], l3);
        }
    }
    __syncthreads();

    if (warp == 0 && lane < T_EFF) {
        int t = lane;
        int c0 = cnti[0], c1 = cnti[1], c2 = cnti[2], c3 = cnti[3];
        for (int j = 0; j < t; j++) {
            int v = tok[j];
            c0 -= (v == 0); c1 -= (v == 1); c2 -= (v == 2); c3 -= (v == 3);
        }
        for (int j = t + L_OUT; j < L_IN; j++) {
            int v = tok[j];
            c0 -= (v == 0); c1 -= (v == 1); c2 -= (v == 2); c3 -= (v == 3);
        }
        d_cnt[bid * 128 + t * 4 + 0] = (float)c0;
        d_cnt[bid * 128 + t * 4 + 1] = (float)c1;
        d_cnt[bid * 128 + t * 4 + 2] = (float)c2;
        d_cnt[bid * 128 + t * 4 + 3] = (float)c3;
    }

    for (int pr = warp; pr < 36; pr += 32) {
        const int v = pr / KS, k1 = pr % KS;
        float s = 0.f;
        #pragma unroll
        for (int m = 0; m < 4; m++) {
            int c0 = lane + 32 * m;
            s += ws[c0 * KS + k1] * es[v * D + c0];
        }
        s = warp_sum(s);
        if (lane == 0) d_g1T[pr * D + bid] = s;
    }
}

// ---------------------------------------------------------------------------
// pre2: c2 = bid. g2T + bb2.
__global__ __launch_bounds__(1024) void k_pre2(
    const float* __restrict__ w2, const float* __restrict__ b1,
    const float* __restrict__ b2)
{
    __shared__ float ws[ROW];
    const int bid = blockIdx.x, tid = threadIdx.x;
    const int lane = tid & 31, warp = tid >> 5;

    cudaTriggerProgrammaticLaunchCompletion();

    const float* wrow = w2 + bid * ROW;
    for (int i = tid; i < ROW; i += 1024) ws[i] = wrow[i];

    cudaGridDependencySynchronize();
    __syncthreads();

    for (int pr = warp; pr < 69; pr += 32) {
        if (pr < 68) {
            const int v = pr / T12, t = pr % T12;
            const int klo = (t > KS - 1) ? t - (KS - 1) : 0;
            const int khi = (t < KS - 1) ? t : KS - 1;
            float s = 0.f;
            for (int k2 = klo; k2 <= khi; k2++) {
                const int k1 = t - k2;
                const float* g1r = d_g1T + (v * KS + k1) * D;
                #pragma unroll
                for (int m = 0; m < 4; m++) {
                    int c1 = lane + 32 * m;
                    s += ws[c1 * KS + k2] * g1r[c1];
                }
            }
            s = warp_sum(s);
            if (lane == 0) d_g2T[(v * T12 + t) * D + bid] = s;
        } else {
            float s = 0.f;
            #pragma unroll 4
            for (int i = 0; i < 36; i++) {
                int idx = lane + 32 * i;
                s += ws[idx] * b1[idx / KS];
            }
            s = warp_sum(s);
            if (lane == 0) d_bb2[bid] = b2[bid] + s;
        }
    }
}

// ---------------------------------------------------------------------------
// pre3: c3 = bid. G + beff.
__global__ __launch_bounds__(1024) void k_pre3(
    const float* __restrict__ w3, const float* __restrict__ b3)
{
    __shared__ float ws[ROW];
    const int bid = blockIdx.x, tid = threadIdx.x;
    const int lane = tid & 31, warp = tid >> 5;

    cudaTriggerProgrammaticLaunchCompletion();

    const float* wrow = w3 + bid * ROW;
    for (int i = tid; i < ROW; i += 1024) ws[i] = wrow[i];

    cudaGridDependencySynchronize();
    __syncthreads();

    for (int pr = warp; pr < 101; pr += 32) {
        if (pr < 100) {
            const int v = pr & 3, t = pr >> 2;
            const int klo = (t > T12 - 1) ? t - (T12 - 1) : 0;
            const int khi = (t < KS - 1) ? t : KS - 1;
            float s = 0.f;
            for (int k3 = klo; k3 <= khi; k3++) {
                const int t12 = t - k3;
                const float* g2r = d_g2T + (v * T12 + t12) * D;
                #pragma unroll
                for (int m = 0; m < 4; m++) {
                    int c2 = lane + 32 * m;
                    s += ws[c2 * KS + k3] * g2r[c2];
                }
            }
            s = warp_sum(s);
            if (lane == 0) d_G[(t * 4 + v) * D + bid] = s;
        } else {
            float s = 0.f;
            #pragma unroll 4
            for (int i = 0; i < 36; i++) {
                int idx = lane + 32 * i;
                s += ws[idx] * d_bb2[idx / KS];
            }
            s = warp_sum(s);
            if (lane == 0) d_beff[bid] = b3[bid] + s;
        }
    }
}

// ---------------------------------------------------------------------------
// Main kernel: 2 CTAs (512 thr) per batch row, halves of the sequence.
// NO clusters: exchange via gmem + generation pair-barrier. 2 CTAs/SM overlap.
__global__ __launch_bounds__(512, 2) void k_main(
    const float* __restrict__ wq, const float* __restrict__ bq,
    const float* __restrict__ wk,
    const float* __restrict__ wv, const float* __restrict__ bv,
    float* __restrict__ out)
{
    __shared__ __align__(16) float sc[2048];   // own half e-weights (padded)
    __shared__ float Hq[6 * 256];
    __shared__ float Hs[128];
    __shared__ float As[128];
    __shared__ __align__(16) float cntf[128];
    __shared__ float rm[128];
    __shared__ float qv[128];
    __shared__ float kq[128];
    __shared__ float sv[128];
    __shared__ float scr[512];
    __shared__ float part[14 * 12];
    __shared__ float redf[40];
    __shared__ float xbuf[80];
    __shared__ float peerb[80];
    __shared__ __align__(16) unsigned tok_u[1032];
    __shared__ __align__(16) unsigned pat_u[1032];

    const int bid = blockIdx.x;
    const int b = bid >> 1, h = bid & 1;
    const int tid = threadIdx.x;
    const int lane = tid & 31, warp = tid >> 5;

    const float SCL = 0.088388347648318447f * 1.4426950408889634f;

    cudaGridDependencySynchronize();

    // Load pre-staged token data (full row).
    for (int i = tid; i < 258; i += 512) {
        ((int4*)tok_u)[i] = ((const int4*)(d_tok + b * 1032))[i];
        ((int4*)pat_u)[i] = ((const int4*)(d_pat + b * 1032))[i];
    }
    if (tid < 32) ((float4*)cntf)[tid] = ((const float4*)(d_cnt + b * 128))[tid];
    __syncthreads();

    // rm[x] = beff[x] + (1/L) * sum_i cnt_i * G[i][x]   (4 partials of 25)
    {
        int pt = tid >> 7, x = tid & 127;
        int i0 = pt * 25;
        float acc = 0.f;
        for (int i = i0; i < i0 + 25; i++) acc += cntf[i] * d_G[i * D + x];
        scr[pt * 128 + x] = acc;
    }
    __syncthreads();
    if (tid < D) {
        float acc = scr[tid] + scr[128 + tid] + scr[256 + tid] + scr[384 + tid];
        rm[tid] = d_beff[tid] + acc * (1.0f / (float)L_OUT);
    }
    __syncthreads();

    // q = Wq @ rm + bq   (16 warps x 8 rows)
    for (int c = warp; c < D; c += 16) {
        float s = 0.f;
        #pragma unroll
        for (int m = 0; m < 4; m++) { int x = lane + 32 * m; s += wq[c * D + x] * rm[x]; }
        s = warp_sum(s);
        if (lane == 0) qv[c] = s + bq[c];
    }
    __syncthreads();

    // kq[x] = sum_c Wk[c][x] * q[c]   (4 partials of 32 rows)
    {
        int g = tid >> 7, x = tid & 127;
        float s = 0.f;
        #pragma unroll
        for (int o = 0; o < 32; o++) s += wk[(g * 32 + o) * D + x] * qv[g * 32 + o];
        scr[g * 128 + x] = s;
    }
    __syncthreads();
    if (tid < D)
        kq[tid] = scr[tid] + scr[128 + tid] + scr[256 + tid] + scr[384 + tid];
    __syncthreads();

    // Hs[i] = SCL * (G[i,:] . kq)
    for (int i = warp; i < 100; i += 16) {
        float s = 0.f;
        #pragma unroll
        for (int m = 0; m < 4; m++) {
            int x = lane + 32 * m;
            s += kq[x] * d_G[i * D + x];
        }
        s = warp_sum(s);
        if (lane == 0) Hs[i] = s * SCL;
    }
    __syncthreads();

    // quad tables (log2 units)
    for (int e = tid; e < 6 * 256; e += 512) {
        int q = e >> 8, idx = e & 255;
        Hq[e] = Hs[(4 * q + 0) * 4 + ((idx >> 6) & 3)]
              + Hs[(4 * q + 1) * 4 + ((idx >> 4) & 3)]
              + Hs[(4 * q + 2) * 4 + ((idx >> 2) & 3)]
              + Hs[(4 * q + 3) * 4 + (idx & 3)];
    }
    __syncthreads();

    // per-table maxima
    if (warp < 6) {
        float m = -1e30f;
        #pragma unroll
        for (int r = 0; r < 8; r++) m = fmaxf(m, Hq[warp * 256 + lane + 32 * r]);
        #pragma unroll
        for (int o = 16; o; o >>= 1) m = fmaxf(m, __shfl_xor_sync(0xffffffffu, m, o));
        if (lane == 0) redf[warp] = m;
    } else if (warp == 6) {
        float m = (lane < 4) ? Hs[96 + lane] : -1e30f;
        #pragma unroll
        for (int o = 16; o; o >>= 1) m = fmaxf(m, __shfl_xor_sync(0xffffffffu, m, o));
        if (lane == 0) redf[6] = m;
    }
    __syncthreads();

    // exponentiate tables in place
    for (int e = tid; e < 6 * 256; e += 512)
        Hq[e] = exp2f(Hq[e] - redf[e >> 8]);
    if (tid < 4)
        Hs[96 + tid] = exp2f(Hs[96 + tid] - redf[6]);
    __syncthreads();

    // scores for OWN HALF: l in [h*HALF, h*HALF + HALF)
    float lsum = 0.f;
    if (tid < HW) {
        const int widx = h * HW + tid;        // word index of l0 = widx*4
        unsigned pw[6];
        #pragma unroll
        for (int q = 0; q < 6; q++) pw[q] = pat_u[widx + q];
        unsigned u6 = tok_u[widx + 6];
        const int l0 = tid * 4;               // local slot
        #pragma unroll
        for (int k = 0; k < 4; k++) {
            float e = Hq[0 * 256 + __byte_perm(pw[0], 0, 0x4440 + k)];
            e *= Hq[1 * 256 + __byte_perm(pw[1], 0, 0x4440 + k)];
            e *= Hq[2 * 256 + __byte_perm(pw[2], 0, 0x4440 + k)];
            e *= Hq[3 * 256 + __byte_perm(pw[3], 0, 0x4440 + k)];
            e *= Hq[4 * 256 + __byte_perm(pw[4], 0, 0x4440 + k)];
            e *= Hq[5 * 256 + __byte_perm(pw[5], 0, 0x4440 + k)];
            e *= Hs[96 + ((u6 >> (8 * k)) & 3)];
            sc[l0 + k] = e;
            lsum += e;
        }
    } else {
        int base = tid * 4;                   // zero pad [2036,2048)
        sc[base + 0] = 0.f; sc[base + 1] = 0.f;
        sc[base + 2] = 0.f; sc[base + 3] = 0.f;
    }
    lsum = warp_sum(lsum);
    if (lane == 0) redf[16 + warp] = lsum;
    __syncthreads();
    if (tid < 32) {
        float m = (tid < 16) ? redf[16 + tid] : 0.f;
        m = warp_sum(m);
        if (tid == 0) xbuf[75] = m;           // partial Z
    }

    // Phase 6 (own half): warp = g(0..6) x s(0..1), 8 iters each.
    const float4* sc4 = (const float4*)sc;
    if (warp < 14) {
        const int g = warp >> 1, s = warp & 1;
        float a[4][3];
        #pragma unroll
        for (int r = 0; r < 4; r++)
            #pragma unroll
            for (int c = 0; c < 3; c++) a[r][c] = 0.f;
        #pragma unroll 2
        for (int it = 0; it < 8; it++) {
            const int lw = s * 256 + it * 32 + lane;        // 0..511
            float4 e4 = sc4[lw];
            const int tw = h * HW + lw + g;
            unsigned u0 = tok_u[tw], u1 = tok_u[tw + 1];
            float m0[7], m1[7], m2[7];
            #pragma unroll
            for (int j = 0; j < 7; j++) {
                int v = (j < 4) ? ((u0 >> (8 * j)) & 3) : ((u1 >> (8 * (j - 4))) & 3);
                m0[j] = (v == 0) ? 1.f : 0.f;
                m1[j] = (v == 1) ? 1.f : 0.f;
                m2[j] = (v == 2) ? 1.f : 0.f;
            }
            const float ev[4] = { e4.x, e4.y, e4.z, e4.w };
            if (g < 6) {
                #pragma unroll
                for (int r = 0; r < 4; r++) {
                    #pragma unroll
                    for (int k = 0; k < 4; k++) {
                        const int j = k + r;
                        a[r][0] += m0[j] * ev[k];
                        a[r][1] += m1[j] * ev[k];
                        a[r][2] += m2[j] * ev[k];
                    }
                }
            } else {
                #pragma unroll
                for (int k = 0; k < 4; k++) {
                    a[0][0] += m0[k] * ev[k];
                    a[0][1] += m1[k] * ev[k];
                    a[0][2] += m2[k] * ev[k];
                }
            }
        }
        #pragma unroll
        for (int r = 0; r < 4; r++)
            #pragma unroll
            for (int c = 0; c < 3; c++) a[r][c] = warp_sum(a[r][c]);
        if (lane == 0) {
            float* p = &part[(g * 2 + s) * 12];
            #pragma unroll
            for (int r = 0; r < 4; r++) {
                p[r * 3 + 0] = a[r][0];
                p[r * 3 + 1] = a[r][1];
                p[r * 3 + 2] = a[r][2];
            }
        }
    }
    __syncthreads();
    if (tid < T_EFF) {
        const int t = tid, g = t >> 2, r = t & 3;
        const float* p0 = &part[(g * 2 + 0) * 12 + r * 3];
        const float* p1 = &part[(g * 2 + 1) * 12 + r * 3];
        xbuf[t * 3 + 0] = p0[0] + p1[0];
        xbuf[t * 3 + 1] = p0[1] + p1[1];
        xbuf[t * 3 + 2] = p0[2] + p1[2];
    }
    __syncthreads();

    // Publish own partials, pair-barrier, read peer's.
    if (tid < 76) d_xch[(b * 2 + h) * 80 + tid] = xbuf[tid];
    __syncthreads();
    if (tid == 0) {
        __threadfence();
        volatile unsigned* vg = p_gen;
        unsigned g0 = vg[b];
        unsigned old = atomicAdd(&p_cnt[b], 1u);
        if (old == 1u) {
            p_cnt[b] = 0u;
            __threadfence();
            atomicAdd(&p_gen[b], 1u);
        } else {
            while (vg[b] == g0) { }
        }
        __threadfence();
    }
    __syncthreads();
    if (tid < 76) peerb[tid] = d_xch[(b * 2 + (h ^ 1)) * 80 + tid];
    __syncthreads();

    const float Z = xbuf[75] + peerb[75];
    const float invZ = 1.0f / Z;
    if (tid < T_EFF) {
        const int t = tid;
        float s0 = xbuf[t * 3 + 0] + peerb[t * 3 + 0];
        float s1 = xbuf[t * 3 + 1] + peerb[t * 3 + 1];
        float s2 = xbuf[t * 3 + 2] + peerb[t * 3 + 2];
        As[t * 4 + 0] = s0; As[t * 4 + 1] = s1;
        As[t * 4 + 2] = s2; As[t * 4 + 3] = Z - s0 - s1 - s2;
    }
    __syncthreads();

    // sv[x] = beff[x] + invZ * sum_i A_i * G[i][x]   (4 partials of 25)
    {
        int pt = tid >> 7, x = tid & 127;
        int i0 = pt * 25;
        float acc = 0.f;
        for (int i = i0; i < i0 + 25; i++) acc += As[i] * d_G[i * D + x];
        scr[pt * 128 + x] = acc;
    }
    __syncthreads();
    if (tid < D) {
        float acc = scr[tid] + scr[128 + tid] + scr[256 + tid] + scr[384 + tid];
        sv[tid] = d_beff[tid] + acc * invZ;
    }
    __syncthreads();

    // out: this CTA writes channels [h*64, h*64+64)
    for (int c0 = warp; c0 < 64; c0 += 16) {
        const int c = h * 64 + c0;
        float s = 0.f;
        #pragma unroll
        for (int m = 0; m < 4; m++) { int x = lane + 32 * m; s += wv[c * D + x] * sv[x]; }
        s = warp_sum(s);
        if (lane == 0) out[b * D + c] = s + bv[c];
    }
}

// ---------------------------------------------------------------------------
static inline void launch_pdl(const void* func, dim3 grid, dim3 block,
                              void** args) {
    cudaLaunchConfig_t cfg = {};
    cfg.gridDim = grid;
    cfg.blockDim = block;
    cfg.dynamicSmemBytes = 0;
    cfg.stream = 0;
    cudaLaunchAttribute attr[1];
    attr[0].id = cudaLaunchAttributeProgrammaticStreamSerialization;
    attr[0].val.programmaticStreamSerializationAllowed = 1;
    cfg.attrs = attr;
    cfg.numAttrs = 1;
    cudaLaunchKernelExC(&cfg, func, args);
}

extern "C" void kernel_launch(void* const* d_in, const int* in_sizes, int n_in,
                              void* d_out, int out_size) {
    const int*   tokens = (const int*)  d_in[0];
    const float* emb    = (const float*)d_in[1];
    const float* w1     = (const float*)d_in[2];
    const float* b1     = (const float*)d_in[3];
    const float* wr     = (const float*)d_in[4];
    const float* br     = (const float*)d_in[5];
    const float* wq     = (const float*)d_in[6];
    const float* bq     = (const float*)d_in[7];
    const float* wk     = (const float*)d_in[8];
    const float* wv     = (const float*)d_in[10];
    const float* bv     = (const float*)d_in[11];

    const float* w2 = wr;
    const float* w3 = wr + D * D * KS;
    const float* b2 = br;
    const float* b3 = br + D;
    float* outp = (float*)d_out;

    k_pre1<<<128, 1024>>>(w1, emb, tokens);
    {
        void* a2[] = { (void*)&w2, (void*)&b1, (void*)&b2 };
        launch_pdl((const void*)k_pre2, dim3(128), dim3(1024), a2);
    }
    {
        void* a3[] = { (void*)&w3, (void*)&b3 };
        launch_pdl((const void*)k_pre3, dim3(128), dim3(1024), a3);
    }
    {
        void* am[] = { (void*)&wq, (void*)&bq, (void*)&wk,
                       (void*)&wv, (void*)&bv, (void*)&outp };
        launch_pdl((const void*)k_main, dim3(2 * BATCH), dim3(512), am);
    }
}

// round 17
// speedup vs baseline: 1.3290x; 1.3290x over previous
#include <cuda_runtime.h>

#define D      128
#define KS     9
#define L_IN   4096
#define L_OUT  4072
#define T_EFF  25
#define T12    17
#define BATCH  128
#define ROW    (D * KS)   // 1152

// Inter-phase tables
__device__ float d_g1T[36 * D];
__device__ float d_g2T[68 * D];
__device__ float d_G  [100 * D];
__device__ float d_bb2[D];
__device__ float d_beff[D];
// Token-side precomputed per row (written by pre2's pre-sync region)
__device__ __align__(16) unsigned d_tok[BATCH * 1032];
__device__ __align__(16) unsigned d_pat[BATCH * 1032];
__device__ __align__(16) float    d_cnt[BATCH * 128];

__device__ __forceinline__ float warp_sum(float s) {
    #pragma unroll
    for (int o = 16; o; o >>= 1) s += __shfl_xor_sync(0xffffffffu, s, o);
    return s;
}

// ---------------------------------------------------------------------------
// pre1: g1 ONLY (short kernel so pre2 can flow in quickly).
__global__ __launch_bounds__(1024) void k_pre1(
    const float* __restrict__ w1, const float* __restrict__ emb)
{
    __shared__ float ws[ROW];
    __shared__ float es[4 * D];
    const int bid = blockIdx.x, tid = threadIdx.x;
    const int lane = tid & 31, warp = tid >> 5;

    cudaTriggerProgrammaticLaunchCompletion();

    const float* wrow = w1 + bid * ROW;
    for (int i = tid; i < ROW; i += 1024) ws[i] = wrow[i];
    if (tid < 512) es[tid] = emb[tid];
    __syncthreads();
    for (int pr = warp; pr < 36; pr += 32) {
        const int v = pr / KS, k1 = pr % KS;
        float s = 0.f;
        #pragma unroll
        for (int m = 0; m < 4; m++) {
            int c0 = lane + 32 * m;
            s += ws[c0 * KS + k1] * es[v * D + c0];
        }
        s = warp_sum(s);
        if (lane == 0) d_g1T[pr * D + bid] = s;
    }
}

// ---------------------------------------------------------------------------
// pre2: PRE-SYNC: all token preprocessing for row bid (independent of pre1).
//       POST-SYNC: g2T + bb2.
__global__ __launch_bounds__(1024) void k_pre2(
    const float* __restrict__ w2, const float* __restrict__ b1,
    const float* __restrict__ b2, const int* __restrict__ tokens)
{
    __shared__ float ws[ROW];
    __shared__ unsigned tok_u[1032];
    __shared__ int cnti[4];
    unsigned char* tok = (unsigned char*)tok_u;

    const int bid = blockIdx.x, tid = threadIdx.x;
    const int lane = tid & 31, warp = tid >> 5;

    cudaTriggerProgrammaticLaunchCompletion();

    // ---- stage own weight row (independent of pre1)
    const float* wrow = w2 + bid * ROW;
    for (int i = tid; i < ROW; i += 1024) ws[i] = wrow[i];

    // ---- token preprocessing (independent of pre1) ----
    {
        const int4* tb4 = (const int4*)(tokens + bid * L_IN);
        int4 w = tb4[tid];
        unsigned pk = (unsigned)w.x | ((unsigned)w.y << 8) |
                      ((unsigned)w.z << 16) | ((unsigned)w.w << 24);
        tok_u[tid] = pk;
        d_tok[bid * 1032 + tid] = pk;
    }
    if (tid < 8) { tok_u[1024 + tid] = 0; d_tok[bid * 1032 + 1024 + tid] = 0; }
    if (tid < 4) cnti[tid] = 0;
    __syncthreads();

    // quad patterns -> global
    for (int i = tid; i < 1030; i += 1024) {
        unsigned w0 = tok_u[i], w1w = tok_u[i + 1];
        unsigned p0 = ((w0 & 0x03030303u) * 0x40100401u) >> 24;
        unsigned f1 = __funnelshift_r(w0, w1w, 8);
        unsigned p1 = ((f1 & 0x03030303u) * 0x40100401u) >> 24;
        unsigned f2 = __funnelshift_r(w0, w1w, 16);
        unsigned p2 = ((f2 & 0x03030303u) * 0x40100401u) >> 24;
        unsigned f3 = __funnelshift_r(w0, w1w, 24);
        unsigned p3 = ((f3 & 0x03030303u) * 0x40100401u) >> 24;
        d_pat[bid * 1032 + i] = p0 | (p1 << 8) | (p2 << 16) | (p3 << 24);
    }
    if (tid < 2) d_pat[bid * 1032 + 1030 + tid] = 0;

    // full counts
    {
        unsigned u = tok_u[tid];
        int l0 = 0, l1 = 0, l2 = 0, l3 = 0;
        #pragma unroll
        for (int j = 0; j < 4; j++) {
            int v = (u >> (8 * j)) & 3;
            l0 += (v == 0); l1 += (v == 1); l2 += (v == 2); l3 += (v == 3);
        }
        #pragma unroll
        for (int o = 16; o; o >>= 1) {
            l0 += __shfl_xor_sync(0xffffffffu, l0, o);
            l1 += __shfl_xor_sync(0xffffffffu, l1, o);
            l2 += __shfl_xor_sync(0xffffffffu, l2, o);
            l3 += __shfl_xor_sync(0xffffffffu, l3, o);
        }
        if (lane == 0) {
            atomicAdd(&cnti[0], l0); atomicAdd(&cnti[1], l1);
            atomicAdd(&cnti[2], l2); atomicAdd(&cnti[3], l3);
        }
    }
    __syncthreads();

    // windowed counts -> global
    if (warp == 0 && lane < T_EFF) {
        int t = lane;
        int c0 = cnti[0], c1 = cnti[1], c2 = cnti[2], c3 = cnti[3];
        for (int j = 0; j < t; j++) {
            int v = tok[j];
            c0 -= (v == 0); c1 -= (v == 1); c2 -= (v == 2); c3 -= (v == 3);
        }
        for (int j = t + L_OUT; j < L_IN; j++) {
            int v = tok[j];
            c0 -= (v == 0); c1 -= (v == 1); c2 -= (v == 2); c3 -= (v == 3);
        }
        d_cnt[bid * 128 + t * 4 + 0] = (float)c0;
        d_cnt[bid * 128 + t * 4 + 1] = (float)c1;
        d_cnt[bid * 128 + t * 4 + 2] = (float)c2;
        d_cnt[bid * 128 + t * 4 + 3] = (float)c3;
    }

    // ---- wait for pre1 (g1T), then g2 dots ----
    cudaGridDependencySynchronize();
    __syncthreads();

    for (int pr = warp; pr < 69; pr += 32) {
        if (pr < 68) {
            const int v = pr / T12, t = pr % T12;
            const int klo = (t > KS - 1) ? t - (KS - 1) : 0;
            const int khi = (t < KS - 1) ? t : KS - 1;
            float s = 0.f;
            for (int k2 = klo; k2 <= khi; k2++) {
                const int k1 = t - k2;
                const float* g1r = d_g1T + (v * KS + k1) * D;
                #pragma unroll
                for (int m = 0; m < 4; m++) {
                    int c1 = lane + 32 * m;
                    s += ws[c1 * KS + k2] * g1r[c1];
                }
            }
            s = warp_sum(s);
            if (lane == 0) d_g2T[(v * T12 + t) * D + bid] = s;
        } else {
            float s = 0.f;
            #pragma unroll 4
            for (int i = 0; i < 36; i++) {
                int idx = lane + 32 * i;
                s += ws[idx] * b1[idx / KS];
            }
            s = warp_sum(s);
            if (lane == 0) d_bb2[bid] = b2[bid] + s;
        }
    }
}

// ---------------------------------------------------------------------------
// pre3: c3 = bid. G + beff. Prologue overlaps pre2 via PDL.
__global__ __launch_bounds__(1024) void k_pre3(
    const float* __restrict__ w3, const float* __restrict__ b3)
{
    __shared__ float ws[ROW];
    const int bid = blockIdx.x, tid = threadIdx.x;
    const int lane = tid & 31, warp = tid >> 5;

    cudaTriggerProgrammaticLaunchCompletion();

    const float* wrow = w3 + bid * ROW;
    for (int i = tid; i < ROW; i += 1024) ws[i] = wrow[i];

    cudaGridDependencySynchronize();
    __syncthreads();

    for (int pr = warp; pr < 101; pr += 32) {
        if (pr < 100) {
            const int v = pr & 3, t = pr >> 2;
            const int klo = (t > T12 - 1) ? t - (T12 - 1) : 0;
            const int khi = (t < KS - 1) ? t : KS - 1;
            float s = 0.f;
            for (int k3 = klo; k3 <= khi; k3++) {
                const int t12 = t - k3;
                const float* g2r = d_g2T + (v * T12 + t12) * D;
                #pragma unroll
                for (int m = 0; m < 4; m++) {
                    int c2 = lane + 32 * m;
                    s += ws[c2 * KS + k3] * g2r[c2];
                }
            }
            s = warp_sum(s);
            if (lane == 0) d_G[(t * 4 + v) * D + bid] = s;
        } else {
            float s = 0.f;
            #pragma unroll 4
            for (int i = 0; i < 36; i++) {
                int idx = lane + 32 * i;
                s += ws[idx] * d_bb2[idx / KS];
            }
            s = warp_sum(s);
            if (lane == 0) d_beff[bid] = b3[bid] + s;
        }
    }
}

// ---------------------------------------------------------------------------
// Main kernel: one CTA per batch row (R15 version, unchanged).
__global__ __launch_bounds__(1024) void k_main(
    const float* __restrict__ wq, const float* __restrict__ bq,
    const float* __restrict__ wk,
    const float* __restrict__ wv, const float* __restrict__ bv,
    float* __restrict__ out)
{
    __shared__ __align__(16) float sc[4096];
    __shared__ float Hq[6 * 256];
    __shared__ float Hs[128];
    __shared__ float As[128];
    __shared__ __align__(16) float cntf[128];
    __shared__ float rm[128];
    __shared__ float qv[128];
    __shared__ float kq[128];
    __shared__ float sv[128];
    __shared__ float part[7 * 4 * 12];
    __shared__ float redf[40];
    __shared__ __align__(16) unsigned tok_u[1032];
    __shared__ __align__(16) unsigned pat_u[1032];

    const int b = blockIdx.x, tid = threadIdx.x;
    const int lane = tid & 31, warp = tid >> 5;

    const float SCL = 0.088388347648318447f * 1.4426950408889634f;

    cudaGridDependencySynchronize();

    if (tid < 258) {
        ((int4*)tok_u)[tid] = ((const int4*)(d_tok + b * 1032))[tid];
    } else if (tid < 516) {
        ((int4*)pat_u)[tid - 258] = ((const int4*)(d_pat + b * 1032))[tid - 258];
    } else if (tid < 548) {
        ((float4*)cntf)[tid - 516] = ((const float4*)(d_cnt + b * 128))[tid - 516];
    }
    __syncthreads();

    // rm[x] = beff[x] + (1/L) * sum_i cnt_i * G[i][x]
    {
        int pt = tid >> 7, x = tid & 127;
        int i0 = pt * 13, i1 = (pt == 7) ? 100 : i0 + 13;
        float acc = 0.f;
        for (int i = i0; i < i1; i++) acc += cntf[i] * d_G[i * D + x];
        sc[pt * 128 + x] = acc;
    }
    __syncthreads();
    if (tid < D) {
        float acc = 0.f;
        #pragma unroll
        for (int p = 0; p < 8; p++) acc += sc[p * 128 + tid];
        rm[tid] = d_beff[tid] + acc * (1.0f / (float)L_OUT);
    }
    __syncthreads();

    // q = Wq @ rm + bq
    for (int c = warp; c < D; c += 32) {
        float s = 0.f;
        #pragma unroll
        for (int m = 0; m < 4; m++) { int x = lane + 32 * m; s += wq[c * D + x] * rm[x]; }
        s = warp_sum(s);
        if (lane == 0) qv[c] = s + bq[c];
    }
    __syncthreads();

    // kq[x] = sum_c Wk[c][x] * q[c]
    {
        int g = tid >> 7, x = tid & 127;
        float s = 0.f;
        #pragma unroll
        for (int o = 0; o < 16; o++) s += wk[(g * 16 + o) * D + x] * qv[g * 16 + o];
        sc[g * D + x] = s;
    }
    __syncthreads();
    if (tid < D) {
        float s = 0.f;
        #pragma unroll
        for (int g = 0; g < 8; g++) s += sc[g * D + tid];
        kq[tid] = s;
    }
    __syncthreads();

    // Hs[i] = SCL * (G[i,:] . kq)
    for (int i = warp; i < 100; i += 32) {
        float s = 0.f;
        #pragma unroll
        for (int m = 0; m < 4; m++) {
            int x = lane + 32 * m;
            s += kq[x] * d_G[i * D + x];
        }
        s = warp_sum(s);
        if (lane == 0) Hs[i] = s * SCL;
    }
    __syncthreads();

    // quad tables (log2 units)
    for (int e = tid; e < 6 * 256; e += 1024) {
        int q = e >> 8, idx = e & 255;
        Hq[e] = Hs[(4 * q + 0) * 4 + ((idx >> 6) & 3)]
              + Hs[(4 * q + 1) * 4 + ((idx >> 4) & 3)]
              + Hs[(4 * q + 2) * 4 + ((idx >> 2) & 3)]
              + Hs[(4 * q + 3) * 4 + (idx & 3)];
    }
    __syncthreads();

    // per-table maxima
    if (warp < 6) {
        float m = -1e30f;
        #pragma unroll
        for (int r = 0; r < 8; r++) m = fmaxf(m, Hq[warp * 256 + lane + 32 * r]);
        #pragma unroll
        for (int o = 16; o; o >>= 1) m = fmaxf(m, __shfl_xor_sync(0xffffffffu, m, o));
        if (lane == 0) redf[warp] = m;
    } else if (warp == 6) {
        float m = (lane < 4) ? Hs[96 + lane] : -1e30f;
        #pragma unroll
        for (int o = 16; o; o >>= 1) m = fmaxf(m, __shfl_xor_sync(0xffffffffu, m, o));
        if (lane == 0) redf[6] = m;
    }
    __syncthreads();

    // exponentiate tables in place
    for (int e = tid; e < 6 * 256; e += 1024)
        Hq[e] = exp2f(Hq[e] - redf[e >> 8]);
    if (tid < 4)
        Hs[96 + tid] = exp2f(Hs[96 + tid] - redf[6]);
    __syncthreads();

    // scores -> e-weights + sum (pure products)
    float lsum = 0.f;
    if (tid < 1018) {
        unsigned pw[6];
        #pragma unroll
        for (int q = 0; q < 6; q++) pw[q] = pat_u[tid + q];
        unsigned u6 = tok_u[tid + 6];
        const int l0 = tid * 4;
        #pragma unroll
        for (int k = 0; k < 4; k++) {
            float e = Hq[0 * 256 + __byte_perm(pw[0], 0, 0x4440 + k)];
            e *= Hq[1 * 256 + __byte_perm(pw[1], 0, 0x4440 + k)];
            e *= Hq[2 * 256 + __byte_perm(pw[2], 0, 0x4440 + k)];
            e *= Hq[3 * 256 + __byte_perm(pw[3], 0, 0x4440 + k)];
            e *= Hq[4 * 256 + __byte_perm(pw[4], 0, 0x4440 + k)];
            e *= Hq[5 * 256 + __byte_perm(pw[5], 0, 0x4440 + k)];
            e *= Hs[96 + ((u6 >> (8 * k)) & 3)];
            sc[l0 + k] = e;
            lsum += e;
        }
    } else {
        int base = 4072 + (tid - 1018) * 4;
        sc[base + 0] = 0.f; sc[base + 1] = 0.f;
        sc[base + 2] = 0.f; sc[base + 3] = 0.f;
    }
    lsum = warp_sum(lsum);
    if (lane == 0) redf[warp] = lsum;
    __syncthreads();
    if (tid < 32) {
        float m = redf[tid];
        m = warp_sum(m);
        if (tid == 0) redf[34] = m;
    }
    __syncthreads();
    const float Z = redf[34];
    const float invZ = 1.0f / Z;

    // Phase 6: tap-grouped A — classify each byte once, FFMA with float masks.
    const float4* sc4 = (const float4*)sc;
    if (warp < 28) {
        const int g = warp >> 2, s = warp & 3;
        float a[4][3];
        #pragma unroll
        for (int r = 0; r < 4; r++)
            #pragma unroll
            for (int c = 0; c < 3; c++) a[r][c] = 0.f;
        #pragma unroll 2
        for (int it = 0; it < 8; it++) {
            const int lw = s * 256 + it * 32 + lane;
            float4 e4 = sc4[lw];
            unsigned u0 = tok_u[lw + g], u1 = tok_u[lw + g + 1];
            float m0[7], m1[7], m2[7];
            #pragma unroll
            for (int j = 0; j < 7; j++) {
                int v = (j < 4) ? ((u0 >> (8 * j)) & 3) : ((u1 >> (8 * (j - 4))) & 3);
                m0[j] = (v == 0) ? 1.f : 0.f;
                m1[j] = (v == 1) ? 1.f : 0.f;
                m2[j] = (v == 2) ? 1.f : 0.f;
            }
            const float ev[4] = { e4.x, e4.y, e4.z, e4.w };
            if (g < 6) {
                #pragma unroll
                for (int r = 0; r < 4; r++) {
                    #pragma unroll
                    for (int k = 0; k < 4; k++) {
                        const int j = k + r;
                        a[r][0] += m0[j] * ev[k];
                        a[r][1] += m1[j] * ev[k];
                        a[r][2] += m2[j] * ev[k];
                    }
                }
            } else {
                #pragma unroll
                for (int k = 0; k < 4; k++) {
                    a[0][0] += m0[k] * ev[k];
                    a[0][1] += m1[k] * ev[k];
                    a[0][2] += m2[k] * ev[k];
                }
            }
        }
        #pragma unroll
        for (int r = 0; r < 4; r++)
            #pragma unroll
            for (int c = 0; c < 3; c++) a[r][c] = warp_sum(a[r][c]);
        if (lane == 0) {
            float* p = &part[(g * 4 + s) * 12];
            #pragma unroll
            for (int r = 0; r < 4; r++) {
                p[r * 3 + 0] = a[r][0];
                p[r * 3 + 1] = a[r][1];
                p[r * 3 + 2] = a[r][2];
            }
        }
    }
    __syncthreads();
    if (tid < T_EFF) {
        const int t = tid, g = t >> 2, r = t & 3;
        float s0 = 0.f, s1 = 0.f, s2 = 0.f;
        #pragma unroll
        for (int s_ = 0; s_ < 4; s_++) {
            const float* p = &part[(g * 4 + s_) * 12 + r * 3];
            s0 += p[0]; s1 += p[1]; s2 += p[2];
        }
        As[t * 4 + 0] = s0; As[t * 4 + 1] = s1;
        As[t * 4 + 2] = s2; As[t * 4 + 3] = Z - s0 - s1 - s2;
    }
    __syncthreads();

    // sv[x] = beff[x] + invZ * sum_i A_i * G[i][x]
    {
        int pt = tid >> 7, x = tid & 127;
        int i0 = pt * 13, i1 = (pt == 7) ? 100 : i0 + 13;
        float acc = 0.f;
        for (int i = i0; i < i1; i++) acc += As[i] * d_G[i * D + x];
        sc[pt * 128 + x] = acc;
    }
    __syncthreads();
    if (tid < D) {
        float acc = 0.f;
        #pragma unroll
        for (int p = 0; p < 8; p++) acc += sc[p * 128 + tid];
        sv[tid] = d_beff[tid] + acc * invZ;
    }
    __syncthreads();

    // out = Wv @ sv + bv
    for (int c = warp; c < D; c += 32) {
        float s = 0.f;
        #pragma unroll
        for (int m = 0; m < 4; m++) { int x = lane + 32 * m; s += wv[c * D + x] * sv[x]; }
        s = warp_sum(s);
        if (lane == 0) out[b * D + c] = s + bv[c];
    }
}

// ---------------------------------------------------------------------------
static inline void launch_pdl(const void* func, dim3 grid, dim3 block,
                              void** args) {
    cudaLaunchConfig_t cfg = {};
    cfg.gridDim = grid;
    cfg.blockDim = block;
    cfg.dynamicSmemBytes = 0;
    cfg.stream = 0;
    cudaLaunchAttribute attr[1];
    attr[0].id = cudaLaunchAttributeProgrammaticStreamSerialization;
    attr[0].val.programmaticStreamSerializationAllowed = 1;
    cfg.attrs = attr;
    cfg.numAttrs = 1;
    cudaLaunchKernelExC(&cfg, func, args);
}

extern "C" void kernel_launch(void* const* d_in, const int* in_sizes, int n_in,
                              void* d_out, int out_size) {
    const int*   tokens = (const int*)  d_in[0];
    const float* emb    = (const float*)d_in[1];
    const float* w1     = (const float*)d_in[2];
    const float* b1     = (const float*)d_in[3];
    const float* wr     = (const float*)d_in[4];
    const float* br     = (const float*)d_in[5];
    const float* wq     = (const float*)d_in[6];
    const float* bq     = (const float*)d_in[7];
    const float* wk     = (const float*)d_in[8];
    const float* wv     = (const float*)d_in[10];
    const float* bv     = (const float*)d_in[11];

    const float* w2 = wr;
    const float* w3 = wr + D * D * KS;
    const float* b2 = br;
    const float* b3 = br + D;
    float* outp = (float*)d_out;

    k_pre1<<<128, 1024>>>(w1, emb);
    {
        void* a2[] = { (void*)&w2, (void*)&b1, (void*)&b2, (void*)&tokens };
        launch_pdl((const void*)k_pre2, dim3(128), dim3(1024), a2);
    }
    {
        void* a3[] = { (void*)&w3, (void*)&b3 };
        launch_pdl((const void*)k_pre3, dim3(128), dim3(1024), a3);
    }
    {
        void* am[] = { (void*)&wq, (void*)&bq, (void*)&wk,
                       (void*)&wv, (void*)&bv, (void*)&outp };
        launch_pdl((const void*)k_main, dim3(BATCH), dim3(1024), am);
    }
}